// round 14
// baseline (speedup 1.0000x reference)
#include <cuda_runtime.h>
#include <math.h>

#define BB 8192
#define NSTEPS 96
#define PER 24
#define NOUTS 804

// scratch (static device arrays: allocation-free)
static __device__ float g_Sin[NSTEPS * BB];        // S at start of step s
static __device__ float g_c[NSTEPS * BB];          // DF*S*sig_S*dW per step
static __device__ float g_Ssnap[4 * BB];           // S after each maturity block
static __device__ float g_Cs[4 * BB];              // sum of c over each block
static __device__ float g_Fpart[8 * 64 * BB];      // per (m,half) summed feats
static __device__ double g_Pm[832 * 256];          // partial payoff sums
static __device__ double g_Ps[832 * 256];          // partial payoff sq-sums
static __device__ float g_dummy[4];

// f32 constants matching the reference's f32 usage
#define DTF  0.020833333333333332f
#define SQDT 0.14433756729740643f
#define DFF  0.99895887568f
#define RFRF 0.05f

// ---- f32x2 packed helpers (sm_103a FFMA2) ----
__device__ __forceinline__ unsigned long long f2_pack(float lo, float hi) {
    unsigned long long r;
    asm("mov.b64 %0, {%1, %2};" : "=l"(r) : "f"(lo), "f"(hi));
    return r;
}
__device__ __forceinline__ void f2_unpack(unsigned long long v, float& lo, float& hi) {
    asm("mov.b64 {%0, %1}, %2;" : "=f"(lo), "=f"(hi) : "l"(v));
}
__device__ __forceinline__ unsigned long long f2_fma(unsigned long long a,
                                                     unsigned long long b,
                                                     unsigned long long c) {
    unsigned long long d;
    asm("fma.rn.f32x2 %0, %1, %2, %3;" : "=l"(d) : "l"(a), "l"(b), "l"(c));
    return d;
}

// --- zero g_Fpart before hedge accumulates into it ---
__global__ void zero_fpart() {
    int i = blockIdx.x * 1024 + threadIdx.x;
    g_Fpart[i] = 0.0f;
    if (i == 0) g_dummy[0] = 1.0f;
}

// ---------------------------------------------------------------------------
// Kernel A (v6): sequential path simulation.
// thread = (net, quarter, lane16): 192 threads = 3 x 4 x 16; each thread
// computes 8 rows/layer (4 row-pairs) for TWO paths. Grid 256 blocks.
// ---------------------------------------------------------------------------
__global__ void __launch_bounds__(192) sim_kernel(
    const float* __restrict__ nW0, const float* __restrict__ nb0,
    const float* __restrict__ nW1, const float* __restrict__ nb1,
    const float* __restrict__ nW2, const float* __restrict__ nb2,
    const float* __restrict__ nW3, const float* __restrict__ nb3,
    const float* __restrict__ rho, const float* __restrict__ V0,
    const float* __restrict__ n1g, const float* __restrict__ n2g)
{
    __shared__ __align__(16) float sW0[3][96];
    __shared__ float sB0[3][32];
    __shared__ __align__(16) float sW1[3][1024];
    __shared__ __align__(16) float sW2[3][1024];
    __shared__ float sB1[3][32], sB2[3][32];
    __shared__ __align__(16) float sW3[3][32];
    __shared__ float sB3[3];
    __shared__ unsigned long long sXa[3][16][32];   // [net][row-pair][path]
    __shared__ unsigned long long sXb[3][16][32];
    __shared__ float sVal[3][32];

    const int tid  = threadIdx.x;
    const int lane = tid & 15;          // 0..15
    const int grp  = tid >> 4;          // 0..11
    const int net  = grp >> 2;          // 0..2
    const int q    = grp & 3;           // 0..3
    const int bA   = blockIdx.x * 32 + lane;
    const int bB   = bA + 16;

    float SA = 100.0f, SB = 100.0f;
    float VA = V0[0],  VB = VA;
    const float rho_s = rho[0];
    const float rho_c = sqrtf(1.0f - rho_s * rho_s);
    const unsigned long long zz = f2_pack(0.0f, 0.0f);

    float csumA = 0.0f, csumB = 0.0f;   // used by grp==0

    for (int m = 0; m < 4; ++m) {
        __syncthreads();
        for (int i = tid; i < 3 * 96; i += 192) {
            int n = i / 96, r = i - 96 * n;
            sW0[n][r] = nW0[(n * 4 + m) * 96 + r];
        }
        for (int i = tid; i < 3 * 1024; i += 192) {
            int n = i >> 10, r = i & 1023;
            sW1[n][r] = nW1[(n * 4 + m) * 1024 + r];
            sW2[n][r] = nW2[(n * 4 + m) * 1024 + r];
        }
        for (int i = tid; i < 3 * 32; i += 192) {
            int n = i >> 5, r = i & 31;
            sB0[n][r] = nb0[(n * 4 + m) * 32 + r];
            sB1[n][r] = nb1[(n * 4 + m) * 32 + r];
            sB2[n][r] = nb2[(n * 4 + m) * 32 + r];
            sW3[n][r] = nW3[(n * 4 + m) * 32 + r];
        }
        if (tid < 3) sB3[tid] = nb3[tid * 4 + m];
        __syncthreads();

        for (int it = 0; it < PER; ++it) {
            const int s = m * PER + it;
            const float t = (float)s * DTF;

            // L0: 16 neuron pairs for both paths (duplicated across quarters)
            unsigned long long hpA[16], hpB[16];
            #pragma unroll
            for (int p = 0; p < 16; ++p) {
                const int o = 2 * p;
                const float wa0 = sW0[net][3 * o],     wb0 = sW0[net][3 * o + 1],
                            wc0 = sW0[net][3 * o + 2];
                const float wa1 = sW0[net][3 * o + 3], wb1 = sW0[net][3 * o + 4],
                            wc1 = sW0[net][3 * o + 5];
                const float b0v = sB0[net][o], b1v = sB0[net][o + 1];
                float eA0 = fmaxf(b0v + wa0 * t + wb0 * SA + wc0 * VA, 0.0f);
                float eA1 = fmaxf(b1v + wa1 * t + wb1 * SA + wc1 * VA, 0.0f);
                float eB0 = fmaxf(b0v + wa0 * t + wb0 * SB + wc0 * VB, 0.0f);
                float eB1 = fmaxf(b1v + wa1 * t + wb1 * SB + wc1 * VB, 0.0f);
                hpA[p] = f2_pack(eA0, eA1);
                hpB[p] = f2_pack(eB0, eB1);
            }

            // L1: this quarter's 4 row-pairs -> sXa (both paths)
            #pragma unroll 2
            for (int p = 0; p < 4; ++p) {
                const int oA = q * 8 + 2 * p;
                const ulonglong2* wA = reinterpret_cast<const ulonglong2*>(&sW1[net][oA * 32]);
                const ulonglong2* wB = reinterpret_cast<const ulonglong2*>(&sW1[net][(oA + 1) * 32]);
                unsigned long long a0 = zz, a1 = zz, b0 = zz, b1 = zz;
                unsigned long long c0 = zz, c1 = zz, d0 = zz, d1 = zz;
                #pragma unroll
                for (int k = 0; k < 8; ++k) {
                    ulonglong2 wva = wA[k];
                    ulonglong2 wvb = wB[k];
                    a0 = f2_fma(wva.x, hpA[2 * k], a0);
                    a1 = f2_fma(wva.y, hpA[2 * k + 1], a1);
                    b0 = f2_fma(wvb.x, hpA[2 * k], b0);
                    b1 = f2_fma(wvb.y, hpA[2 * k + 1], b1);
                    c0 = f2_fma(wva.x, hpB[2 * k], c0);
                    c1 = f2_fma(wva.y, hpB[2 * k + 1], c1);
                    d0 = f2_fma(wvb.x, hpB[2 * k], d0);
                    d1 = f2_fma(wvb.y, hpB[2 * k + 1], d1);
                }
                float p0, p1, p2, p3;
                const float biasA = sB1[net][oA], biasB = sB1[net][oA + 1];
                f2_unpack(a0, p0, p1); f2_unpack(a1, p2, p3);
                float xA0 = fmaxf(biasA + ((p0 + p1) + (p2 + p3)), 0.0f);
                f2_unpack(b0, p0, p1); f2_unpack(b1, p2, p3);
                float xA1 = fmaxf(biasB + ((p0 + p1) + (p2 + p3)), 0.0f);
                f2_unpack(c0, p0, p1); f2_unpack(c1, p2, p3);
                float xB0 = fmaxf(biasA + ((p0 + p1) + (p2 + p3)), 0.0f);
                f2_unpack(d0, p0, p1); f2_unpack(d1, p2, p3);
                float xB1 = fmaxf(biasB + ((p0 + p1) + (p2 + p3)), 0.0f);
                sXa[net][q * 4 + p][lane]      = f2_pack(xA0, xA1);
                sXa[net][q * 4 + p][lane + 16] = f2_pack(xB0, xB1);
            }
            __syncthreads();

            // L2: read 16 pairs (both paths), compute this quarter's 4 row-pairs
            unsigned long long hqA[16], hqB[16];
            #pragma unroll
            for (int k = 0; k < 16; ++k) {
                hqA[k] = sXa[net][k][lane];
                hqB[k] = sXa[net][k][lane + 16];
            }
            #pragma unroll 2
            for (int p = 0; p < 4; ++p) {
                const int oA = q * 8 + 2 * p;
                const ulonglong2* wA = reinterpret_cast<const ulonglong2*>(&sW2[net][oA * 32]);
                const ulonglong2* wB = reinterpret_cast<const ulonglong2*>(&sW2[net][(oA + 1) * 32]);
                unsigned long long a0 = zz, a1 = zz, b0 = zz, b1 = zz;
                unsigned long long c0 = zz, c1 = zz, d0 = zz, d1 = zz;
                #pragma unroll
                for (int k = 0; k < 8; ++k) {
                    ulonglong2 wva = wA[k];
                    ulonglong2 wvb = wB[k];
                    a0 = f2_fma(wva.x, hqA[2 * k], a0);
                    a1 = f2_fma(wva.y, hqA[2 * k + 1], a1);
                    b0 = f2_fma(wvb.x, hqA[2 * k], b0);
                    b1 = f2_fma(wvb.y, hqA[2 * k + 1], b1);
                    c0 = f2_fma(wva.x, hqB[2 * k], c0);
                    c1 = f2_fma(wva.y, hqB[2 * k + 1], c1);
                    d0 = f2_fma(wvb.x, hqB[2 * k], d0);
                    d1 = f2_fma(wvb.y, hqB[2 * k + 1], d1);
                }
                float p0, p1, p2, p3;
                const float biasA = sB2[net][oA], biasB = sB2[net][oA + 1];
                f2_unpack(a0, p0, p1); f2_unpack(a1, p2, p3);
                float xA0 = fmaxf(biasA + ((p0 + p1) + (p2 + p3)), 0.0f);
                f2_unpack(b0, p0, p1); f2_unpack(b1, p2, p3);
                float xA1 = fmaxf(biasB + ((p0 + p1) + (p2 + p3)), 0.0f);
                f2_unpack(c0, p0, p1); f2_unpack(c1, p2, p3);
                float xB0 = fmaxf(biasA + ((p0 + p1) + (p2 + p3)), 0.0f);
                f2_unpack(d0, p0, p1); f2_unpack(d1, p2, p3);
                float xB1 = fmaxf(biasB + ((p0 + p1) + (p2 + p3)), 0.0f);
                sXb[net][q * 4 + p][lane]      = f2_pack(xA0, xA1);
                sXb[net][q * 4 + p][lane + 16] = f2_pack(xB0, xB1);
            }
            __syncthreads();

            // L3: quarter 0 computes scalar outputs for both paths
            if (q == 0) {
                const ulonglong2* w = reinterpret_cast<const ulonglong2*>(&sW3[net][0]);
                unsigned long long a0 = zz, a1 = zz, c0 = zz, c1 = zz;
                #pragma unroll
                for (int k = 0; k < 8; ++k) {
                    ulonglong2 wv = w[k];
                    a0 = f2_fma(wv.x, sXb[net][2 * k][lane], a0);
                    a1 = f2_fma(wv.y, sXb[net][2 * k + 1][lane], a1);
                    c0 = f2_fma(wv.x, sXb[net][2 * k][lane + 16], c0);
                    c1 = f2_fma(wv.y, sXb[net][2 * k + 1][lane + 16], c1);
                }
                float r0, r1, r2, r3;
                f2_unpack(a0, r0, r1); f2_unpack(a1, r2, r3);
                float rawA = sB3[net] + ((r0 + r1) + (r2 + r3));
                f2_unpack(c0, r0, r1); f2_unpack(c1, r2, r3);
                float rawB = sB3[net] + ((r0 + r1) + (r2 + r3));
                sVal[net][lane]      = rawA / (1.0f + fabsf(rawA) * SQDT);
                sVal[net][lane + 16] = rawB / (1.0f + fabsf(rawB) * SQDT);
            }
            __syncthreads();

            const float v0A = sVal[0][lane], v0B = sVal[0][lane + 16];
            const float v1A = sVal[1][lane], v1B = sVal[1][lane + 16];
            const float v2A = sVal[2][lane], v2B = sVal[2][lane + 16];

            const float z1A = n1g[s * BB + bA], z1B = n1g[s * BB + bB];
            const float z2A = n2g[s * BB + bA], z2B = n2g[s * BB + bB];
            const float dWA = SQDT * z2A, dWB = SQDT * z2B;
            const float dBA = rho_s * dWA + rho_c * SQDT * z1A;
            const float dBB = rho_s * dWB + rho_c * SQDT * z1B;
            const float srA = SA * RFRF, srB = SB * RFRF;
            const float bSA = srA / (1.0f + fabsf(srA) * SQDT);
            const float bSB = srB / (1.0f + fabsf(srB) * SQDT);

            if (grp == 0) {
                g_Sin[s * BB + bA] = SA;
                g_Sin[s * BB + bB] = SB;
                const float ccA = DFF * SA * v0A * dWA;
                const float ccB = DFF * SB * v0B * dWB;
                g_c[s * BB + bA] = ccA;
                g_c[s * BB + bB] = ccB;
                csumA += ccA;
                csumB += ccB;
            }
            SA = SA + bSA * DTF + v0A * dBA;
            VA = fmaxf(VA + v1A * DTF + v2A * dWA, 0.0f);
            SB = SB + bSB * DTF + v0B * dBB;
            VB = fmaxf(VB + v1B * DTF + v2B * dWB, 0.0f);
        }
        if (grp == 0) {
            g_Ssnap[m * BB + bA] = SA;
            g_Ssnap[m * BB + bB] = SB;
            g_Cs[m * BB + bA] = csumA;
            g_Cs[m * BB + bB] = csumB;
            csumA = 0.0f;
            csumB = 0.0f;
        }
    }
}

// ---------------------------------------------------------------------------
// Kernel B (v7): hedge trunk, FFMA2 + 2 paths/thread + 8 warps/SM.
// ---------------------------------------------------------------------------
__global__ void __launch_bounds__(256) hedge_kernel(
    const float* __restrict__ hW0, const float* __restrict__ hb0,
    const float* __restrict__ hW1, const float* __restrict__ hb1,
    const float* __restrict__ hW2, const float* __restrict__ hb2,
    const float* __restrict__ hW3, const float* __restrict__ hb3)
{
    extern __shared__ float sm[];
    float* w0   = sm;            // 128
    float* b0s  = w0 + 128;      // 64
    float* b1s  = b0s + 64;      // 64
    float* b2s  = b1s + 64;      // 64
    float* b3s  = b2s + 64;      // 64
    float* wT1  = b3s + 64;      // 4096  [j][o]  (o consecutive)
    float* wT2  = wT1 + 4096;    // 4096  [j][o]
    float* w3   = wT2 + 4096;    // 4096  [o][j]  (j consecutive)
    unsigned long long* xbufU = reinterpret_cast<unsigned long long*>(w3 + 4096); // 64*256 u64

    const int tid  = threadIdx.x;
    const int by   = blockIdx.y;        // 0..7 = m*2 + half
    const int m    = by >> 1;
    const int s0   = m * PER + (by & 1) * 12;
    const int bA   = blockIdx.x * 512 + tid;   // path 0
    const int bB   = bA + 256;                 // path 1

    if (tid < 64) {
        b0s[tid] = hb0[m * 64 + tid];
        b1s[tid] = hb1[m * 64 + tid];
        b2s[tid] = hb2[m * 64 + tid];
        b3s[tid] = hb3[m * 64 + tid];
    } else if (tid < 192) {
        w0[tid - 64] = hW0[m * 128 + tid - 64];
    }
    for (int i = tid; i < 4096; i += 256) {
        int o = i >> 6, j = i & 63;
        wT1[j * 64 + o] = hW1[m * 4096 + i];
        wT2[j * 64 + o] = hW2[m * 4096 + i];
        w3[i] = hW3[m * 4096 + i];
    }
    __syncthreads();

    const unsigned long long zz = f2_pack(0.0f, 0.0f);

    #pragma unroll 1
    for (int it = 0; it < 12; ++it) {
        const int s = s0 + it;
        const float t = (float)s * DTF;
        const float SA = g_Sin[s * BB + bA];
        const float SB = g_Sin[s * BB + bB];
        const float cA = g_c[s * BB + bA];
        const float cB = g_c[s * BB + bB];

        unsigned long long yA[32], yB[32];   // neuron pairs for each path

        // ---- L1 (j-loop, L0 inline) ----
        {
            const ulonglong2* bv = reinterpret_cast<const ulonglong2*>(b1s);
            #pragma unroll
            for (int k = 0; k < 16; ++k) {
                ulonglong2 v = bv[k];
                yA[2 * k] = v.x; yA[2 * k + 1] = v.y;
                yB[2 * k] = v.x; yB[2 * k + 1] = v.y;
            }
        }
        #pragma unroll 2
        for (int j = 0; j < 64; ++j) {
            const float w0a = w0[2 * j], w0b = w0[2 * j + 1], bj = b0s[j];
            const float xjA = fmaxf(bj + w0a * t + w0b * SA, 0.0f);
            const float xjB = fmaxf(bj + w0a * t + w0b * SB, 0.0f);
            const unsigned long long xpA = f2_pack(xjA, xjA);
            const unsigned long long xpB = f2_pack(xjB, xjB);
            const ulonglong2* w = reinterpret_cast<const ulonglong2*>(&wT1[j * 64]);
            #pragma unroll
            for (int k = 0; k < 16; ++k) {
                ulonglong2 wv = w[k];
                yA[2 * k]     = f2_fma(wv.x, xpA, yA[2 * k]);
                yA[2 * k + 1] = f2_fma(wv.y, xpA, yA[2 * k + 1]);
                yB[2 * k]     = f2_fma(wv.x, xpB, yB[2 * k]);
                yB[2 * k + 1] = f2_fma(wv.y, xpB, yB[2 * k + 1]);
            }
        }
        // relu -> own smem column, repacked ACROSS PATHS: xbufU[j] = {xA_j, xB_j}
        #pragma unroll
        for (int p = 0; p < 32; ++p) {
            float a0, a1, c0, c1;
            f2_unpack(yA[p], a0, a1);
            f2_unpack(yB[p], c0, c1);
            xbufU[(2 * p) * 256 + tid]     = f2_pack(fmaxf(a0, 0.0f), fmaxf(c0, 0.0f));
            xbufU[(2 * p + 1) * 256 + tid] = f2_pack(fmaxf(a1, 0.0f), fmaxf(c1, 0.0f));
        }

        // ---- L2 (j-loop over xbuf) ----
        {
            const ulonglong2* bv = reinterpret_cast<const ulonglong2*>(b2s);
            #pragma unroll
            for (int k = 0; k < 16; ++k) {
                ulonglong2 v = bv[k];
                yA[2 * k] = v.x; yA[2 * k + 1] = v.y;
                yB[2 * k] = v.x; yB[2 * k + 1] = v.y;
            }
        }
        #pragma unroll 2
        for (int j = 0; j < 64; ++j) {
            float xjA, xjB;
            f2_unpack(xbufU[j * 256 + tid], xjA, xjB);
            const unsigned long long xpA = f2_pack(xjA, xjA);
            const unsigned long long xpB = f2_pack(xjB, xjB);
            const ulonglong2* w = reinterpret_cast<const ulonglong2*>(&wT2[j * 64]);
            #pragma unroll
            for (int k = 0; k < 16; ++k) {
                ulonglong2 wv = w[k];
                yA[2 * k]     = f2_fma(wv.x, xpA, yA[2 * k]);
                yA[2 * k + 1] = f2_fma(wv.y, xpA, yA[2 * k + 1]);
                yB[2 * k]     = f2_fma(wv.x, xpB, yB[2 * k]);
                yB[2 * k + 1] = f2_fma(wv.y, xpB, yB[2 * k + 1]);
            }
        }
        // relu in place (packed)
        #pragma unroll
        for (int p = 0; p < 32; ++p) {
            float lo, hi;
            f2_unpack(yA[p], lo, hi);
            yA[p] = f2_pack(fmaxf(lo, 0.0f), fmaxf(hi, 0.0f));
            f2_unpack(yB[p], lo, hi);
            yB[p] = f2_pack(fmaxf(lo, 0.0f), fmaxf(hi, 0.0f));
        }

        // ---- L3 (o-loop): accumulate into L2-resident global slice ----
        #pragma unroll 2
        for (int o = 0; o < 64; ++o) {
            const ulonglong2* w = reinterpret_cast<const ulonglong2*>(&w3[o * 64]);
            unsigned long long aA0 = zz, aA1 = zz, aB0 = zz, aB1 = zz;
            #pragma unroll
            for (int k = 0; k < 16; ++k) {
                ulonglong2 wv = w[k];
                aA0 = f2_fma(wv.x, yA[2 * k], aA0);
                aA1 = f2_fma(wv.y, yA[2 * k + 1], aA1);
                aB0 = f2_fma(wv.x, yB[2 * k], aB0);
                aB1 = f2_fma(wv.y, yB[2 * k + 1], aB1);
            }
            float p0, p1, p2, p3, q0, q1, q2, q3;
            f2_unpack(aA0, p0, p1); f2_unpack(aA1, p2, p3);
            f2_unpack(aB0, q0, q1); f2_unpack(aB1, q2, q3);
            const float bo = b3s[o];
            float hA = fmaxf(bo + ((p0 + p1) + (p2 + p3)), 0.0f);
            float hB = fmaxf(bo + ((q0 + q1) + (q2 + q3)), 0.0f);
            const size_t idx = (size_t)(by * 64 + o) * BB + bA;
            g_Fpart[idx]       += cA * hA;
            g_Fpart[idx + 256] += cB * hB;
        }
    }
}

// ---------------------------------------------------------------------------
// Kernel C (v4): fused gemm + H + payoff statistics.
// block = (64 o-rows starting at m0 = by*64, 256 paths). Loops q=0..3
// accumulating acc[o] += W4[q]row_o . Fsum[q][:,n] ONLY for q <= m(o)
// (m(o) = o&3 compile-time since m0 % 4 == 0). Then forms H, payoff, and
// deterministic warp-level fp64 partial sums -> g_Pm/g_Ps[o][xb*8+warp].
// ---------------------------------------------------------------------------
__global__ void __launch_bounds__(256) gemmstat_kernel(
    const float* __restrict__ hW4, const float* __restrict__ hb4,
    const float* __restrict__ strikes)
{
    __shared__ __align__(16) float As[64 * 64];   // W4[q] rows for this o-tile
    __shared__ float sStr[201];
    __shared__ float sB4[4 * 64];

    const int tid = threadIdx.x;
    const int m0  = blockIdx.y * 64;
    const int xb  = blockIdx.x;
    const int n   = xb * 256 + tid;

    for (int i = tid; i < 201; i += 256) sStr[i] = strikes[i];
    {
        int qq = tid >> 6, oo = tid & 63;
        int o = m0 + oo;
        sB4[tid] = (o < NOUTS) ? hb4[qq * NOUTS + o] : 0.0f;
    }

    float acc[64];
    #pragma unroll
    for (int oo = 0; oo < 64; ++oo) acc[oo] = 0.0f;

    const unsigned long long zz = f2_pack(0.0f, 0.0f);

    #pragma unroll 1
    for (int q = 0; q < 4; ++q) {
        __syncthreads();
        for (int i = tid; i < 64 * 64; i += 256) {
            int oo = i >> 6, o = m0 + oo;
            As[i] = (o < NOUTS) ? hW4[(size_t)(q * NOUTS + o) * 64 + (i & 63)] : 0.0f;
        }
        __syncthreads();

        // Fsum[q] column n, packed into 32 j-pairs
        unsigned long long xU[32];
        #pragma unroll
        for (int p = 0; p < 32; ++p) {
            float a = g_Fpart[(size_t)((2 * q) * 64 + 2 * p) * BB + n]
                    + g_Fpart[(size_t)((2 * q + 1) * 64 + 2 * p) * BB + n];
            float b = g_Fpart[(size_t)((2 * q) * 64 + 2 * p + 1) * BB + n]
                    + g_Fpart[(size_t)((2 * q + 1) * 64 + 2 * p + 1) * BB + n];
            xU[p] = f2_pack(a, b);
        }

        // only o-rows with m(o) >= q participate
        #pragma unroll
        for (int mm = 0; mm < 4; ++mm) {
            if (q <= mm) {
                #pragma unroll
                for (int jj = 0; jj < 16; ++jj) {
                    const int oo = jj * 4 + mm;
                    const ulonglong2* w = reinterpret_cast<const ulonglong2*>(&As[oo * 64]);
                    unsigned long long a0 = zz, a1 = zz;
                    #pragma unroll
                    for (int k = 0; k < 16; ++k) {
                        ulonglong2 wv = w[k];
                        a0 = f2_fma(wv.x, xU[2 * k], a0);
                        a1 = f2_fma(wv.y, xU[2 * k + 1], a1);
                    }
                    float r0, r1, r2, r3;
                    f2_unpack(a0, r0, r1);
                    f2_unpack(a1, r2, r3);
                    acc[oo] += ((r0 + r1) + (r2 + r3));
                }
            }
        }
    }

    // payoff + warp-level partial statistics
    const float Cs0 = g_Cs[n],          Cs1 = g_Cs[BB + n];
    const float Cs2 = g_Cs[2 * BB + n], Cs3 = g_Cs[3 * BB + n];
    const float Sn0 = g_Ssnap[n],          Sn1 = g_Ssnap[BB + n];
    const float Sn2 = g_Ssnap[2 * BB + n], Sn3 = g_Ssnap[3 * BB + n];
    const float d0 = (float)exp(-0.025);
    const float d1 = (float)exp(-0.05);
    const float d2 = (float)exp(-0.075);
    const float d3 = (float)exp(-0.1);

    #pragma unroll
    for (int oo = 0; oo < 64; ++oo) {
        const int o = m0 + oo;
        if (o < NOUTS) {
            const int m = oo & 3;              // compile-time per unrolled oo
            float H = acc[oo] + sB4[oo] * Cs0;
            if (m >= 1) H += sB4[64 + oo] * Cs1;
            if (m >= 2) H += sB4[128 + oo] * Cs2;
            if (m >= 3) H += sB4[192 + oo] * Cs3;
            const float Sm = (m == 0) ? Sn0 : (m == 1) ? Sn1 : (m == 2) ? Sn2 : Sn3;
            const float dc = (m == 0) ? d0 : (m == 1) ? d1 : (m == 2) ? d2 : d3;
            float pay = dc * fmaxf(Sm - sStr[o >> 2], 0.0f) - H;
            double s1 = (double)pay;
            double s2 = (double)pay * (double)pay;
            #pragma unroll
            for (int off = 16; off > 0; off >>= 1) {
                s1 += __shfl_down_sync(0xffffffffu, s1, off);
                s2 += __shfl_down_sync(0xffffffffu, s2, off);
            }
            if ((tid & 31) == 0) {
                const int slot = o * 256 + xb * 8 + (tid >> 5);
                g_Pm[slot] = s1;
                g_Ps[slot] = s2;
            }
        }
    }
}

// ---------------------------------------------------------------------------
// Kernel D (v2): final reduction of 256 partials per (strike, maturity)
// ---------------------------------------------------------------------------
__global__ void __launch_bounds__(256) finstat_kernel(float* __restrict__ out)
{
    const int o = blockIdx.x;          // 0..803
    const int tid = threadIdx.x;
    __shared__ double r1[256], r2[256];
    r1[tid] = g_Pm[o * 256 + tid];
    r2[tid] = g_Ps[o * 256 + tid];
    __syncthreads();
    for (int st = 128; st > 0; st >>= 1) {
        if (tid < st) { r1[tid] += r1[tid + st]; r2[tid] += r2[tid + st]; }
        __syncthreads();
    }
    if (tid == 0) {
        double total = r1[0];
        out[o] = (float)(total / 8192.0);
        out[NOUTS + o] = (float)((r2[0] - total * total / 8192.0) / 8191.0);
    }
}

// ---------------------------------------------------------------------------
extern "C" void kernel_launch(void* const* d_in, const int* in_sizes, int n_in,
                              void* d_out, int out_size)
{
    const float* nW0 = (const float*)d_in[0];
    const float* nb0 = (const float*)d_in[1];
    const float* nW1 = (const float*)d_in[2];
    const float* nb1 = (const float*)d_in[3];
    const float* nW2 = (const float*)d_in[4];
    const float* nb2 = (const float*)d_in[5];
    const float* nW3 = (const float*)d_in[6];
    const float* nb3 = (const float*)d_in[7];
    const float* hW0 = (const float*)d_in[8];
    const float* hb0 = (const float*)d_in[9];
    const float* hW1 = (const float*)d_in[10];
    const float* hb1 = (const float*)d_in[11];
    const float* hW2 = (const float*)d_in[12];
    const float* hb2 = (const float*)d_in[13];
    const float* hW3 = (const float*)d_in[14];
    const float* hb3 = (const float*)d_in[15];
    const float* hW4 = (const float*)d_in[16];
    const float* hb4 = (const float*)d_in[17];
    const float* rho = (const float*)d_in[18];
    const float* V0  = (const float*)d_in[19];
    const float* strikes = (const float*)d_in[20];
    const float* noise1  = (const float*)d_in[21];
    const float* noise2  = (const float*)d_in[22];

    const int hedge_smem = 45440 * (int)sizeof(float);  // 181,760 B
    cudaFuncSetAttribute(hedge_kernel, cudaFuncAttributeMaxDynamicSharedMemorySize,
                         hedge_smem);

    zero_fpart<<<(8 * 64 * BB) / 1024, 1024>>>();
    sim_kernel<<<256, 192>>>(nW0, nb0, nW1, nb1, nW2, nb2, nW3, nb3,
                             rho, V0, noise1, noise2);
    hedge_kernel<<<dim3(16, 8), 256, hedge_smem>>>(hW0, hb0, hW1, hb1,
                                                   hW2, hb2, hW3, hb3);
    gemmstat_kernel<<<dim3(32, 13), 256>>>(hW4, hb4, strikes);
    finstat_kernel<<<NOUTS, 256>>>((float*)d_out);
}

// round 15
// speedup vs baseline: 1.1173x; 1.1173x over previous
#include <cuda_runtime.h>
#include <math.h>

#define BB 8192
#define NSTEPS 96
#define PER 24
#define NOUTS 804

// scratch (static device arrays: allocation-free)
static __device__ float g_Sin[NSTEPS * BB];        // S at start of step s
static __device__ float g_c[NSTEPS * BB];          // DF*S*sig_S*dW per step
static __device__ float g_Ssnap[4 * BB];           // S after each maturity block
static __device__ float g_Cs[4 * BB];              // sum of c over each block
static __device__ float g_Fpart[8 * 64 * BB];      // per (m,half) summed feats
static __device__ float g_H[NOUTS * BB];           // hedge value H[o][b]
static __device__ float g_dummy[4];

// f32 constants matching the reference's f32 usage
#define DTF  0.020833333333333332f
#define SQDT 0.14433756729740643f
#define DFF  0.99895887568f
#define RFRF 0.05f

// ---- f32x2 packed helpers (sm_103a FFMA2) ----
__device__ __forceinline__ unsigned long long f2_pack(float lo, float hi) {
    unsigned long long r;
    asm("mov.b64 %0, {%1, %2};" : "=l"(r) : "f"(lo), "f"(hi));
    return r;
}
__device__ __forceinline__ void f2_unpack(unsigned long long v, float& lo, float& hi) {
    asm("mov.b64 {%0, %1}, %2;" : "=f"(lo), "=f"(hi) : "l"(v));
}
__device__ __forceinline__ unsigned long long f2_fma(unsigned long long a,
                                                     unsigned long long b,
                                                     unsigned long long c) {
    unsigned long long d;
    asm("fma.rn.f32x2 %0, %1, %2, %3;" : "=l"(d) : "l"(a), "l"(b), "l"(c));
    return d;
}

// --- zero g_Fpart before hedge accumulates into it ---
__global__ void zero_fpart() {
    int i = blockIdx.x * 1024 + threadIdx.x;
    g_Fpart[i] = 0.0f;
    if (i == 0) g_dummy[0] = 1.0f;
}

// ---------------------------------------------------------------------------
// Kernel A (v6): sequential path simulation.
// thread = (net, quarter, lane16): 192 threads = 3 x 4 x 16; each thread
// computes 8 rows/layer (4 row-pairs) for TWO paths. Grid 256 blocks.
// ---------------------------------------------------------------------------
__global__ void __launch_bounds__(192) sim_kernel(
    const float* __restrict__ nW0, const float* __restrict__ nb0,
    const float* __restrict__ nW1, const float* __restrict__ nb1,
    const float* __restrict__ nW2, const float* __restrict__ nb2,
    const float* __restrict__ nW3, const float* __restrict__ nb3,
    const float* __restrict__ rho, const float* __restrict__ V0,
    const float* __restrict__ n1g, const float* __restrict__ n2g)
{
    __shared__ __align__(16) float sW0[3][96];
    __shared__ float sB0[3][32];
    __shared__ __align__(16) float sW1[3][1024];
    __shared__ __align__(16) float sW2[3][1024];
    __shared__ float sB1[3][32], sB2[3][32];
    __shared__ __align__(16) float sW3[3][32];
    __shared__ float sB3[3];
    __shared__ unsigned long long sXa[3][16][32];   // [net][row-pair][path]
    __shared__ unsigned long long sXb[3][16][32];
    __shared__ float sVal[3][32];

    const int tid  = threadIdx.x;
    const int lane = tid & 15;          // 0..15
    const int grp  = tid >> 4;          // 0..11
    const int net  = grp >> 2;          // 0..2
    const int q    = grp & 3;           // 0..3
    const int bA   = blockIdx.x * 32 + lane;
    const int bB   = bA + 16;

    float SA = 100.0f, SB = 100.0f;
    float VA = V0[0],  VB = VA;
    const float rho_s = rho[0];
    const float rho_c = sqrtf(1.0f - rho_s * rho_s);
    const unsigned long long zz = f2_pack(0.0f, 0.0f);

    float csumA = 0.0f, csumB = 0.0f;   // used by grp==0

    for (int m = 0; m < 4; ++m) {
        __syncthreads();
        for (int i = tid; i < 3 * 96; i += 192) {
            int n = i / 96, r = i - 96 * n;
            sW0[n][r] = nW0[(n * 4 + m) * 96 + r];
        }
        for (int i = tid; i < 3 * 1024; i += 192) {
            int n = i >> 10, r = i & 1023;
            sW1[n][r] = nW1[(n * 4 + m) * 1024 + r];
            sW2[n][r] = nW2[(n * 4 + m) * 1024 + r];
        }
        for (int i = tid; i < 3 * 32; i += 192) {
            int n = i >> 5, r = i & 31;
            sB0[n][r] = nb0[(n * 4 + m) * 32 + r];
            sB1[n][r] = nb1[(n * 4 + m) * 32 + r];
            sB2[n][r] = nb2[(n * 4 + m) * 32 + r];
            sW3[n][r] = nW3[(n * 4 + m) * 32 + r];
        }
        if (tid < 3) sB3[tid] = nb3[tid * 4 + m];
        __syncthreads();

        for (int it = 0; it < PER; ++it) {
            const int s = m * PER + it;
            const float t = (float)s * DTF;

            // L0: 16 neuron pairs for both paths (duplicated across quarters)
            unsigned long long hpA[16], hpB[16];
            #pragma unroll
            for (int p = 0; p < 16; ++p) {
                const int o = 2 * p;
                const float wa0 = sW0[net][3 * o],     wb0 = sW0[net][3 * o + 1],
                            wc0 = sW0[net][3 * o + 2];
                const float wa1 = sW0[net][3 * o + 3], wb1 = sW0[net][3 * o + 4],
                            wc1 = sW0[net][3 * o + 5];
                const float b0v = sB0[net][o], b1v = sB0[net][o + 1];
                float eA0 = fmaxf(b0v + wa0 * t + wb0 * SA + wc0 * VA, 0.0f);
                float eA1 = fmaxf(b1v + wa1 * t + wb1 * SA + wc1 * VA, 0.0f);
                float eB0 = fmaxf(b0v + wa0 * t + wb0 * SB + wc0 * VB, 0.0f);
                float eB1 = fmaxf(b1v + wa1 * t + wb1 * SB + wc1 * VB, 0.0f);
                hpA[p] = f2_pack(eA0, eA1);
                hpB[p] = f2_pack(eB0, eB1);
            }

            // L1: this quarter's 4 row-pairs -> sXa (both paths)
            #pragma unroll 2
            for (int p = 0; p < 4; ++p) {
                const int oA = q * 8 + 2 * p;
                const ulonglong2* wA = reinterpret_cast<const ulonglong2*>(&sW1[net][oA * 32]);
                const ulonglong2* wB = reinterpret_cast<const ulonglong2*>(&sW1[net][(oA + 1) * 32]);
                unsigned long long a0 = zz, a1 = zz, b0 = zz, b1 = zz;
                unsigned long long c0 = zz, c1 = zz, d0 = zz, d1 = zz;
                #pragma unroll
                for (int k = 0; k < 8; ++k) {
                    ulonglong2 wva = wA[k];
                    ulonglong2 wvb = wB[k];
                    a0 = f2_fma(wva.x, hpA[2 * k], a0);
                    a1 = f2_fma(wva.y, hpA[2 * k + 1], a1);
                    b0 = f2_fma(wvb.x, hpA[2 * k], b0);
                    b1 = f2_fma(wvb.y, hpA[2 * k + 1], b1);
                    c0 = f2_fma(wva.x, hpB[2 * k], c0);
                    c1 = f2_fma(wva.y, hpB[2 * k + 1], c1);
                    d0 = f2_fma(wvb.x, hpB[2 * k], d0);
                    d1 = f2_fma(wvb.y, hpB[2 * k + 1], d1);
                }
                float p0, p1, p2, p3;
                const float biasA = sB1[net][oA], biasB = sB1[net][oA + 1];
                f2_unpack(a0, p0, p1); f2_unpack(a1, p2, p3);
                float xA0 = fmaxf(biasA + ((p0 + p1) + (p2 + p3)), 0.0f);
                f2_unpack(b0, p0, p1); f2_unpack(b1, p2, p3);
                float xA1 = fmaxf(biasB + ((p0 + p1) + (p2 + p3)), 0.0f);
                f2_unpack(c0, p0, p1); f2_unpack(c1, p2, p3);
                float xB0 = fmaxf(biasA + ((p0 + p1) + (p2 + p3)), 0.0f);
                f2_unpack(d0, p0, p1); f2_unpack(d1, p2, p3);
                float xB1 = fmaxf(biasB + ((p0 + p1) + (p2 + p3)), 0.0f);
                sXa[net][q * 4 + p][lane]      = f2_pack(xA0, xA1);
                sXa[net][q * 4 + p][lane + 16] = f2_pack(xB0, xB1);
            }
            __syncthreads();

            // L2: read 16 pairs (both paths), compute this quarter's 4 row-pairs
            unsigned long long hqA[16], hqB[16];
            #pragma unroll
            for (int k = 0; k < 16; ++k) {
                hqA[k] = sXa[net][k][lane];
                hqB[k] = sXa[net][k][lane + 16];
            }
            #pragma unroll 2
            for (int p = 0; p < 4; ++p) {
                const int oA = q * 8 + 2 * p;
                const ulonglong2* wA = reinterpret_cast<const ulonglong2*>(&sW2[net][oA * 32]);
                const ulonglong2* wB = reinterpret_cast<const ulonglong2*>(&sW2[net][(oA + 1) * 32]);
                unsigned long long a0 = zz, a1 = zz, b0 = zz, b1 = zz;
                unsigned long long c0 = zz, c1 = zz, d0 = zz, d1 = zz;
                #pragma unroll
                for (int k = 0; k < 8; ++k) {
                    ulonglong2 wva = wA[k];
                    ulonglong2 wvb = wB[k];
                    a0 = f2_fma(wva.x, hqA[2 * k], a0);
                    a1 = f2_fma(wva.y, hqA[2 * k + 1], a1);
                    b0 = f2_fma(wvb.x, hqA[2 * k], b0);
                    b1 = f2_fma(wvb.y, hqA[2 * k + 1], b1);
                    c0 = f2_fma(wva.x, hqB[2 * k], c0);
                    c1 = f2_fma(wva.y, hqB[2 * k + 1], c1);
                    d0 = f2_fma(wvb.x, hqB[2 * k], d0);
                    d1 = f2_fma(wvb.y, hqB[2 * k + 1], d1);
                }
                float p0, p1, p2, p3;
                const float biasA = sB2[net][oA], biasB = sB2[net][oA + 1];
                f2_unpack(a0, p0, p1); f2_unpack(a1, p2, p3);
                float xA0 = fmaxf(biasA + ((p0 + p1) + (p2 + p3)), 0.0f);
                f2_unpack(b0, p0, p1); f2_unpack(b1, p2, p3);
                float xA1 = fmaxf(biasB + ((p0 + p1) + (p2 + p3)), 0.0f);
                f2_unpack(c0, p0, p1); f2_unpack(c1, p2, p3);
                float xB0 = fmaxf(biasA + ((p0 + p1) + (p2 + p3)), 0.0f);
                f2_unpack(d0, p0, p1); f2_unpack(d1, p2, p3);
                float xB1 = fmaxf(biasB + ((p0 + p1) + (p2 + p3)), 0.0f);
                sXb[net][q * 4 + p][lane]      = f2_pack(xA0, xA1);
                sXb[net][q * 4 + p][lane + 16] = f2_pack(xB0, xB1);
            }
            __syncthreads();

            // L3: quarter 0 computes scalar outputs for both paths
            if (q == 0) {
                const ulonglong2* w = reinterpret_cast<const ulonglong2*>(&sW3[net][0]);
                unsigned long long a0 = zz, a1 = zz, c0 = zz, c1 = zz;
                #pragma unroll
                for (int k = 0; k < 8; ++k) {
                    ulonglong2 wv = w[k];
                    a0 = f2_fma(wv.x, sXb[net][2 * k][lane], a0);
                    a1 = f2_fma(wv.y, sXb[net][2 * k + 1][lane], a1);
                    c0 = f2_fma(wv.x, sXb[net][2 * k][lane + 16], c0);
                    c1 = f2_fma(wv.y, sXb[net][2 * k + 1][lane + 16], c1);
                }
                float r0, r1, r2, r3;
                f2_unpack(a0, r0, r1); f2_unpack(a1, r2, r3);
                float rawA = sB3[net] + ((r0 + r1) + (r2 + r3));
                f2_unpack(c0, r0, r1); f2_unpack(c1, r2, r3);
                float rawB = sB3[net] + ((r0 + r1) + (r2 + r3));
                sVal[net][lane]      = rawA / (1.0f + fabsf(rawA) * SQDT);
                sVal[net][lane + 16] = rawB / (1.0f + fabsf(rawB) * SQDT);
            }
            __syncthreads();

            const float v0A = sVal[0][lane], v0B = sVal[0][lane + 16];
            const float v1A = sVal[1][lane], v1B = sVal[1][lane + 16];
            const float v2A = sVal[2][lane], v2B = sVal[2][lane + 16];

            const float z1A = n1g[s * BB + bA], z1B = n1g[s * BB + bB];
            const float z2A = n2g[s * BB + bA], z2B = n2g[s * BB + bB];
            const float dWA = SQDT * z2A, dWB = SQDT * z2B;
            const float dBA = rho_s * dWA + rho_c * SQDT * z1A;
            const float dBB = rho_s * dWB + rho_c * SQDT * z1B;
            const float srA = SA * RFRF, srB = SB * RFRF;
            const float bSA = srA / (1.0f + fabsf(srA) * SQDT);
            const float bSB = srB / (1.0f + fabsf(srB) * SQDT);

            if (grp == 0) {
                g_Sin[s * BB + bA] = SA;
                g_Sin[s * BB + bB] = SB;
                const float ccA = DFF * SA * v0A * dWA;
                const float ccB = DFF * SB * v0B * dWB;
                g_c[s * BB + bA] = ccA;
                g_c[s * BB + bB] = ccB;
                csumA += ccA;
                csumB += ccB;
            }
            SA = SA + bSA * DTF + v0A * dBA;
            VA = fmaxf(VA + v1A * DTF + v2A * dWA, 0.0f);
            SB = SB + bSB * DTF + v0B * dBB;
            VB = fmaxf(VB + v1B * DTF + v2B * dWB, 0.0f);
        }
        if (grp == 0) {
            g_Ssnap[m * BB + bA] = SA;
            g_Ssnap[m * BB + bB] = SB;
            g_Cs[m * BB + bA] = csumA;
            g_Cs[m * BB + bB] = csumB;
            csumA = 0.0f;
            csumB = 0.0f;
        }
    }
}

// ---------------------------------------------------------------------------
// Kernel B (v7): hedge trunk, FFMA2 + 2 paths/thread + 8 warps/SM.
// ---------------------------------------------------------------------------
__global__ void __launch_bounds__(256) hedge_kernel(
    const float* __restrict__ hW0, const float* __restrict__ hb0,
    const float* __restrict__ hW1, const float* __restrict__ hb1,
    const float* __restrict__ hW2, const float* __restrict__ hb2,
    const float* __restrict__ hW3, const float* __restrict__ hb3)
{
    extern __shared__ float sm[];
    float* w0   = sm;            // 128
    float* b0s  = w0 + 128;      // 64
    float* b1s  = b0s + 64;      // 64
    float* b2s  = b1s + 64;      // 64
    float* b3s  = b2s + 64;      // 64
    float* wT1  = b3s + 64;      // 4096  [j][o]  (o consecutive)
    float* wT2  = wT1 + 4096;    // 4096  [j][o]
    float* w3   = wT2 + 4096;    // 4096  [o][j]  (j consecutive)
    unsigned long long* xbufU = reinterpret_cast<unsigned long long*>(w3 + 4096); // 64*256 u64

    const int tid  = threadIdx.x;
    const int by   = blockIdx.y;        // 0..7 = m*2 + half
    const int m    = by >> 1;
    const int s0   = m * PER + (by & 1) * 12;
    const int bA   = blockIdx.x * 512 + tid;   // path 0
    const int bB   = bA + 256;                 // path 1

    if (tid < 64) {
        b0s[tid] = hb0[m * 64 + tid];
        b1s[tid] = hb1[m * 64 + tid];
        b2s[tid] = hb2[m * 64 + tid];
        b3s[tid] = hb3[m * 64 + tid];
    } else if (tid < 192) {
        w0[tid - 64] = hW0[m * 128 + tid - 64];
    }
    for (int i = tid; i < 4096; i += 256) {
        int o = i >> 6, j = i & 63;
        wT1[j * 64 + o] = hW1[m * 4096 + i];
        wT2[j * 64 + o] = hW2[m * 4096 + i];
        w3[i] = hW3[m * 4096 + i];
    }
    __syncthreads();

    const unsigned long long zz = f2_pack(0.0f, 0.0f);

    #pragma unroll 1
    for (int it = 0; it < 12; ++it) {
        const int s = s0 + it;
        const float t = (float)s * DTF;
        const float SA = g_Sin[s * BB + bA];
        const float SB = g_Sin[s * BB + bB];
        const float cA = g_c[s * BB + bA];
        const float cB = g_c[s * BB + bB];

        unsigned long long yA[32], yB[32];   // neuron pairs for each path

        // ---- L1 (j-loop, L0 inline) ----
        {
            const ulonglong2* bv = reinterpret_cast<const ulonglong2*>(b1s);
            #pragma unroll
            for (int k = 0; k < 16; ++k) {
                ulonglong2 v = bv[k];
                yA[2 * k] = v.x; yA[2 * k + 1] = v.y;
                yB[2 * k] = v.x; yB[2 * k + 1] = v.y;
            }
        }
        #pragma unroll 2
        for (int j = 0; j < 64; ++j) {
            const float w0a = w0[2 * j], w0b = w0[2 * j + 1], bj = b0s[j];
            const float xjA = fmaxf(bj + w0a * t + w0b * SA, 0.0f);
            const float xjB = fmaxf(bj + w0a * t + w0b * SB, 0.0f);
            const unsigned long long xpA = f2_pack(xjA, xjA);
            const unsigned long long xpB = f2_pack(xjB, xjB);
            const ulonglong2* w = reinterpret_cast<const ulonglong2*>(&wT1[j * 64]);
            #pragma unroll
            for (int k = 0; k < 16; ++k) {
                ulonglong2 wv = w[k];
                yA[2 * k]     = f2_fma(wv.x, xpA, yA[2 * k]);
                yA[2 * k + 1] = f2_fma(wv.y, xpA, yA[2 * k + 1]);
                yB[2 * k]     = f2_fma(wv.x, xpB, yB[2 * k]);
                yB[2 * k + 1] = f2_fma(wv.y, xpB, yB[2 * k + 1]);
            }
        }
        // relu -> own smem column, repacked ACROSS PATHS: xbufU[j] = {xA_j, xB_j}
        #pragma unroll
        for (int p = 0; p < 32; ++p) {
            float a0, a1, c0, c1;
            f2_unpack(yA[p], a0, a1);
            f2_unpack(yB[p], c0, c1);
            xbufU[(2 * p) * 256 + tid]     = f2_pack(fmaxf(a0, 0.0f), fmaxf(c0, 0.0f));
            xbufU[(2 * p + 1) * 256 + tid] = f2_pack(fmaxf(a1, 0.0f), fmaxf(c1, 0.0f));
        }

        // ---- L2 (j-loop over xbuf) ----
        {
            const ulonglong2* bv = reinterpret_cast<const ulonglong2*>(b2s);
            #pragma unroll
            for (int k = 0; k < 16; ++k) {
                ulonglong2 v = bv[k];
                yA[2 * k] = v.x; yA[2 * k + 1] = v.y;
                yB[2 * k] = v.x; yB[2 * k + 1] = v.y;
            }
        }
        #pragma unroll 2
        for (int j = 0; j < 64; ++j) {
            float xjA, xjB;
            f2_unpack(xbufU[j * 256 + tid], xjA, xjB);
            const unsigned long long xpA = f2_pack(xjA, xjA);
            const unsigned long long xpB = f2_pack(xjB, xjB);
            const ulonglong2* w = reinterpret_cast<const ulonglong2*>(&wT2[j * 64]);
            #pragma unroll
            for (int k = 0; k < 16; ++k) {
                ulonglong2 wv = w[k];
                yA[2 * k]     = f2_fma(wv.x, xpA, yA[2 * k]);
                yA[2 * k + 1] = f2_fma(wv.y, xpA, yA[2 * k + 1]);
                yB[2 * k]     = f2_fma(wv.x, xpB, yB[2 * k]);
                yB[2 * k + 1] = f2_fma(wv.y, xpB, yB[2 * k + 1]);
            }
        }
        // relu in place (packed)
        #pragma unroll
        for (int p = 0; p < 32; ++p) {
            float lo, hi;
            f2_unpack(yA[p], lo, hi);
            yA[p] = f2_pack(fmaxf(lo, 0.0f), fmaxf(hi, 0.0f));
            f2_unpack(yB[p], lo, hi);
            yB[p] = f2_pack(fmaxf(lo, 0.0f), fmaxf(hi, 0.0f));
        }

        // ---- L3 (o-loop): accumulate into L2-resident global slice ----
        #pragma unroll 2
        for (int o = 0; o < 64; ++o) {
            const ulonglong2* w = reinterpret_cast<const ulonglong2*>(&w3[o * 64]);
            unsigned long long aA0 = zz, aA1 = zz, aB0 = zz, aB1 = zz;
            #pragma unroll
            for (int k = 0; k < 16; ++k) {
                ulonglong2 wv = w[k];
                aA0 = f2_fma(wv.x, yA[2 * k], aA0);
                aA1 = f2_fma(wv.y, yA[2 * k + 1], aA1);
                aB0 = f2_fma(wv.x, yB[2 * k], aB0);
                aB1 = f2_fma(wv.y, yB[2 * k + 1], aB1);
            }
            float p0, p1, p2, p3, q0, q1, q2, q3;
            f2_unpack(aA0, p0, p1); f2_unpack(aA1, p2, p3);
            f2_unpack(aB0, q0, q1); f2_unpack(aB1, q2, q3);
            const float bo = b3s[o];
            float hA = fmaxf(bo + ((p0 + p1) + (p2 + p3)), 0.0f);
            float hB = fmaxf(bo + ((q0 + q1) + (q2 + q3)), 0.0f);
            const size_t idx = (size_t)(by * 64 + o) * BB + bA;
            g_Fpart[idx]       += cA * hA;
            g_Fpart[idx + 256] += cB * hB;
        }
    }
}

// ---------------------------------------------------------------------------
// Kernel C (v5): masked-q GEMM producing H directly (NO statistics tail).
// block = (64 o-rows at m0 = by*64, 256 paths). acc[oo] accumulates
// W4[q]row . Fsum[q] only for q <= m(oo) (m = oo&3, compile-time). Adds
// bias*Cs terms and stores H[o][n]. 37.5% fewer FLOPs than full gemm and
// 4x smaller output (26 MB).
// ---------------------------------------------------------------------------
__global__ void __launch_bounds__(256) gemmH_kernel(
    const float* __restrict__ hW4, const float* __restrict__ hb4)
{
    __shared__ __align__(16) float As[64 * 64];
    __shared__ float sB4[4 * 64];

    const int tid = threadIdx.x;
    const int m0  = blockIdx.y * 64;
    const int n   = blockIdx.x * 256 + tid;

    {
        int qq = tid >> 6, oo = tid & 63;
        int o = m0 + oo;
        sB4[tid] = (o < NOUTS) ? hb4[qq * NOUTS + o] : 0.0f;
    }

    float acc[64];
    #pragma unroll
    for (int oo = 0; oo < 64; ++oo) acc[oo] = 0.0f;

    const unsigned long long zz = f2_pack(0.0f, 0.0f);

    #pragma unroll 1
    for (int q = 0; q < 4; ++q) {
        __syncthreads();
        for (int i = tid; i < 64 * 64; i += 256) {
            int oo = i >> 6, o = m0 + oo;
            As[i] = (o < NOUTS) ? hW4[(size_t)(q * NOUTS + o) * 64 + (i & 63)] : 0.0f;
        }
        __syncthreads();

        unsigned long long xU[32];
        #pragma unroll
        for (int p = 0; p < 32; ++p) {
            float a = g_Fpart[(size_t)((2 * q) * 64 + 2 * p) * BB + n]
                    + g_Fpart[(size_t)((2 * q + 1) * 64 + 2 * p) * BB + n];
            float b = g_Fpart[(size_t)((2 * q) * 64 + 2 * p + 1) * BB + n]
                    + g_Fpart[(size_t)((2 * q + 1) * 64 + 2 * p + 1) * BB + n];
            xU[p] = f2_pack(a, b);
        }

        #pragma unroll
        for (int mm = 0; mm < 4; ++mm) {
            if (q <= mm) {
                #pragma unroll
                for (int jj = 0; jj < 16; ++jj) {
                    const int oo = jj * 4 + mm;
                    const ulonglong2* w = reinterpret_cast<const ulonglong2*>(&As[oo * 64]);
                    unsigned long long a0 = zz, a1 = zz;
                    #pragma unroll
                    for (int k = 0; k < 16; ++k) {
                        ulonglong2 wv = w[k];
                        a0 = f2_fma(wv.x, xU[2 * k], a0);
                        a1 = f2_fma(wv.y, xU[2 * k + 1], a1);
                    }
                    float r0, r1, r2, r3;
                    f2_unpack(a0, r0, r1);
                    f2_unpack(a1, r2, r3);
                    acc[oo] += ((r0 + r1) + (r2 + r3));
                }
            }
        }
    }

    const float Cs0 = g_Cs[n],          Cs1 = g_Cs[BB + n];
    const float Cs2 = g_Cs[2 * BB + n], Cs3 = g_Cs[3 * BB + n];

    #pragma unroll
    for (int oo = 0; oo < 64; ++oo) {
        const int o = m0 + oo;
        if (o < NOUTS) {
            const int m = oo & 3;
            float H = acc[oo] + sB4[oo] * Cs0;
            if (m >= 1) H += sB4[64 + oo] * Cs1;
            if (m >= 2) H += sB4[128 + oo] * Cs2;
            if (m >= 3) H += sB4[192 + oo] * Cs3;
            g_H[(size_t)o * BB + n] = H;
        }
    }
}

// ---------------------------------------------------------------------------
// Kernel D (v3): payoff + mean/variance per (strike, maturity); fp64 acc.
// Reads the single fused H value per path.
// ---------------------------------------------------------------------------
__global__ void __launch_bounds__(512) reduce_kernel(
    const float* __restrict__ strikes, float* __restrict__ out)
{
    const int o = blockIdx.x;          // 0..803, o = k*4 + m
    const int k = o >> 2;
    const int m = o & 3;
    const int tid = threadIdx.x;
    const float disc = (float)exp(-0.025 * (double)(m + 1));
    const float K = strikes[k];

    double sum = 0.0, ss = 0.0;
    for (int b = tid; b < BB; b += 512) {
        float pay = disc * fmaxf(g_Ssnap[m * BB + b] - K, 0.0f) - g_H[(size_t)o * BB + b];
        sum += (double)pay;
        ss += (double)pay * (double)pay;
    }

    __shared__ double r1[512], r2[512];
    r1[tid] = sum; r2[tid] = ss;
    __syncthreads();
    for (int st = 256; st > 0; st >>= 1) {
        if (tid < st) { r1[tid] += r1[tid + st]; r2[tid] += r2[tid + st]; }
        __syncthreads();
    }
    if (tid == 0) {
        double total = r1[0];
        out[o] = (float)(total / 8192.0);
        out[NOUTS + o] = (float)((r2[0] - total * total / 8192.0) / 8191.0);
    }
}

// ---------------------------------------------------------------------------
extern "C" void kernel_launch(void* const* d_in, const int* in_sizes, int n_in,
                              void* d_out, int out_size)
{
    const float* nW0 = (const float*)d_in[0];
    const float* nb0 = (const float*)d_in[1];
    const float* nW1 = (const float*)d_in[2];
    const float* nb1 = (const float*)d_in[3];
    const float* nW2 = (const float*)d_in[4];
    const float* nb2 = (const float*)d_in[5];
    const float* nW3 = (const float*)d_in[6];
    const float* nb3 = (const float*)d_in[7];
    const float* hW0 = (const float*)d_in[8];
    const float* hb0 = (const float*)d_in[9];
    const float* hW1 = (const float*)d_in[10];
    const float* hb1 = (const float*)d_in[11];
    const float* hW2 = (const float*)d_in[12];
    const float* hb2 = (const float*)d_in[13];
    const float* hW3 = (const float*)d_in[14];
    const float* hb3 = (const float*)d_in[15];
    const float* hW4 = (const float*)d_in[16];
    const float* hb4 = (const float*)d_in[17];
    const float* rho = (const float*)d_in[18];
    const float* V0  = (const float*)d_in[19];
    const float* strikes = (const float*)d_in[20];
    const float* noise1  = (const float*)d_in[21];
    const float* noise2  = (const float*)d_in[22];

    const int hedge_smem = 45440 * (int)sizeof(float);  // 181,760 B
    cudaFuncSetAttribute(hedge_kernel, cudaFuncAttributeMaxDynamicSharedMemorySize,
                         hedge_smem);

    zero_fpart<<<(8 * 64 * BB) / 1024, 1024>>>();
    sim_kernel<<<256, 192>>>(nW0, nb0, nW1, nb1, nW2, nb2, nW3, nb3,
                             rho, V0, noise1, noise2);
    hedge_kernel<<<dim3(16, 8), 256, hedge_smem>>>(hW0, hb0, hW1, hb1,
                                                   hW2, hb2, hW3, hb3);
    gemmH_kernel<<<dim3(32, 13), 256>>>(hW4, hb4);
    reduce_kernel<<<NOUTS, 512>>>(strikes, (float*)d_out);
}

// round 16
// speedup vs baseline: 1.1311x; 1.0123x over previous
#include <cuda_runtime.h>
#include <math.h>

#define BB 8192
#define NSTEPS 96
#define PER 24
#define NOUTS 804

// scratch (static device arrays: allocation-free)
static __device__ float g_Sin[NSTEPS * BB];        // S at start of step s
static __device__ float g_c[NSTEPS * BB];          // DF*S*sig_S*dW per step
static __device__ float g_Ssnap[4 * BB];           // S after each maturity block
static __device__ float g_Cs[4 * BB];              // sum of c over each block
static __device__ float g_Fpart[8 * 64 * BB];      // per (m,half) summed feats
static __device__ float g_H[NOUTS * BB];           // hedge value H[o][b]
static __device__ float g_dummy[4];

// f32 constants matching the reference's f32 usage
#define DTF  0.020833333333333332f
#define SQDT 0.14433756729740643f
#define DFF  0.99895887568f
#define RFRF 0.05f

// ---- f32x2 packed helpers (sm_103a FFMA2) ----
__device__ __forceinline__ unsigned long long f2_pack(float lo, float hi) {
    unsigned long long r;
    asm("mov.b64 %0, {%1, %2};" : "=l"(r) : "f"(lo), "f"(hi));
    return r;
}
__device__ __forceinline__ void f2_unpack(unsigned long long v, float& lo, float& hi) {
    asm("mov.b64 {%0, %1}, %2;" : "=f"(lo), "=f"(hi) : "l"(v));
}
__device__ __forceinline__ unsigned long long f2_fma(unsigned long long a,
                                                     unsigned long long b,
                                                     unsigned long long c) {
    unsigned long long d;
    asm("fma.rn.f32x2 %0, %1, %2, %3;" : "=l"(d) : "l"(a), "l"(b), "l"(c));
    return d;
}

// --- zero g_Fpart before hedge accumulates into it ---
__global__ void zero_fpart() {
    int i = blockIdx.x * 1024 + threadIdx.x;
    g_Fpart[i] = 0.0f;
    if (i == 0) g_dummy[0] = 1.0f;
}

// ---------------------------------------------------------------------------
// Kernel A (v6): sequential path simulation.
// thread = (net, quarter, lane16): 192 threads = 3 x 4 x 16; each thread
// computes 8 rows/layer (4 row-pairs) for TWO paths. Grid 256 blocks.
// ---------------------------------------------------------------------------
__global__ void __launch_bounds__(192) sim_kernel(
    const float* __restrict__ nW0, const float* __restrict__ nb0,
    const float* __restrict__ nW1, const float* __restrict__ nb1,
    const float* __restrict__ nW2, const float* __restrict__ nb2,
    const float* __restrict__ nW3, const float* __restrict__ nb3,
    const float* __restrict__ rho, const float* __restrict__ V0,
    const float* __restrict__ n1g, const float* __restrict__ n2g)
{
    __shared__ __align__(16) float sW0[3][96];
    __shared__ float sB0[3][32];
    __shared__ __align__(16) float sW1[3][1024];
    __shared__ __align__(16) float sW2[3][1024];
    __shared__ float sB1[3][32], sB2[3][32];
    __shared__ __align__(16) float sW3[3][32];
    __shared__ float sB3[3];
    __shared__ unsigned long long sXa[3][16][32];   // [net][row-pair][path]
    __shared__ unsigned long long sXb[3][16][32];
    __shared__ float sVal[3][32];

    const int tid  = threadIdx.x;
    const int lane = tid & 15;          // 0..15
    const int grp  = tid >> 4;          // 0..11
    const int net  = grp >> 2;          // 0..2
    const int q    = grp & 3;           // 0..3
    const int bA   = blockIdx.x * 32 + lane;
    const int bB   = bA + 16;

    float SA = 100.0f, SB = 100.0f;
    float VA = V0[0],  VB = VA;
    const float rho_s = rho[0];
    const float rho_c = sqrtf(1.0f - rho_s * rho_s);
    const unsigned long long zz = f2_pack(0.0f, 0.0f);

    float csumA = 0.0f, csumB = 0.0f;   // used by grp==0

    for (int m = 0; m < 4; ++m) {
        __syncthreads();
        for (int i = tid; i < 3 * 96; i += 192) {
            int n = i / 96, r = i - 96 * n;
            sW0[n][r] = nW0[(n * 4 + m) * 96 + r];
        }
        for (int i = tid; i < 3 * 1024; i += 192) {
            int n = i >> 10, r = i & 1023;
            sW1[n][r] = nW1[(n * 4 + m) * 1024 + r];
            sW2[n][r] = nW2[(n * 4 + m) * 1024 + r];
        }
        for (int i = tid; i < 3 * 32; i += 192) {
            int n = i >> 5, r = i & 31;
            sB0[n][r] = nb0[(n * 4 + m) * 32 + r];
            sB1[n][r] = nb1[(n * 4 + m) * 32 + r];
            sB2[n][r] = nb2[(n * 4 + m) * 32 + r];
            sW3[n][r] = nW3[(n * 4 + m) * 32 + r];
        }
        if (tid < 3) sB3[tid] = nb3[tid * 4 + m];
        __syncthreads();

        for (int it = 0; it < PER; ++it) {
            const int s = m * PER + it;
            const float t = (float)s * DTF;

            // L0: 16 neuron pairs for both paths (duplicated across quarters)
            unsigned long long hpA[16], hpB[16];
            #pragma unroll
            for (int p = 0; p < 16; ++p) {
                const int o = 2 * p;
                const float wa0 = sW0[net][3 * o],     wb0 = sW0[net][3 * o + 1],
                            wc0 = sW0[net][3 * o + 2];
                const float wa1 = sW0[net][3 * o + 3], wb1 = sW0[net][3 * o + 4],
                            wc1 = sW0[net][3 * o + 5];
                const float b0v = sB0[net][o], b1v = sB0[net][o + 1];
                float eA0 = fmaxf(b0v + wa0 * t + wb0 * SA + wc0 * VA, 0.0f);
                float eA1 = fmaxf(b1v + wa1 * t + wb1 * SA + wc1 * VA, 0.0f);
                float eB0 = fmaxf(b0v + wa0 * t + wb0 * SB + wc0 * VB, 0.0f);
                float eB1 = fmaxf(b1v + wa1 * t + wb1 * SB + wc1 * VB, 0.0f);
                hpA[p] = f2_pack(eA0, eA1);
                hpB[p] = f2_pack(eB0, eB1);
            }

            // L1: this quarter's 4 row-pairs -> sXa (both paths)
            #pragma unroll 2
            for (int p = 0; p < 4; ++p) {
                const int oA = q * 8 + 2 * p;
                const ulonglong2* wA = reinterpret_cast<const ulonglong2*>(&sW1[net][oA * 32]);
                const ulonglong2* wB = reinterpret_cast<const ulonglong2*>(&sW1[net][(oA + 1) * 32]);
                unsigned long long a0 = zz, a1 = zz, b0 = zz, b1 = zz;
                unsigned long long c0 = zz, c1 = zz, d0 = zz, d1 = zz;
                #pragma unroll
                for (int k = 0; k < 8; ++k) {
                    ulonglong2 wva = wA[k];
                    ulonglong2 wvb = wB[k];
                    a0 = f2_fma(wva.x, hpA[2 * k], a0);
                    a1 = f2_fma(wva.y, hpA[2 * k + 1], a1);
                    b0 = f2_fma(wvb.x, hpA[2 * k], b0);
                    b1 = f2_fma(wvb.y, hpA[2 * k + 1], b1);
                    c0 = f2_fma(wva.x, hpB[2 * k], c0);
                    c1 = f2_fma(wva.y, hpB[2 * k + 1], c1);
                    d0 = f2_fma(wvb.x, hpB[2 * k], d0);
                    d1 = f2_fma(wvb.y, hpB[2 * k + 1], d1);
                }
                float p0, p1, p2, p3;
                const float biasA = sB1[net][oA], biasB = sB1[net][oA + 1];
                f2_unpack(a0, p0, p1); f2_unpack(a1, p2, p3);
                float xA0 = fmaxf(biasA + ((p0 + p1) + (p2 + p3)), 0.0f);
                f2_unpack(b0, p0, p1); f2_unpack(b1, p2, p3);
                float xA1 = fmaxf(biasB + ((p0 + p1) + (p2 + p3)), 0.0f);
                f2_unpack(c0, p0, p1); f2_unpack(c1, p2, p3);
                float xB0 = fmaxf(biasA + ((p0 + p1) + (p2 + p3)), 0.0f);
                f2_unpack(d0, p0, p1); f2_unpack(d1, p2, p3);
                float xB1 = fmaxf(biasB + ((p0 + p1) + (p2 + p3)), 0.0f);
                sXa[net][q * 4 + p][lane]      = f2_pack(xA0, xA1);
                sXa[net][q * 4 + p][lane + 16] = f2_pack(xB0, xB1);
            }
            __syncthreads();

            // L2: read 16 pairs (both paths), compute this quarter's 4 row-pairs
            unsigned long long hqA[16], hqB[16];
            #pragma unroll
            for (int k = 0; k < 16; ++k) {
                hqA[k] = sXa[net][k][lane];
                hqB[k] = sXa[net][k][lane + 16];
            }
            #pragma unroll 2
            for (int p = 0; p < 4; ++p) {
                const int oA = q * 8 + 2 * p;
                const ulonglong2* wA = reinterpret_cast<const ulonglong2*>(&sW2[net][oA * 32]);
                const ulonglong2* wB = reinterpret_cast<const ulonglong2*>(&sW2[net][(oA + 1) * 32]);
                unsigned long long a0 = zz, a1 = zz, b0 = zz, b1 = zz;
                unsigned long long c0 = zz, c1 = zz, d0 = zz, d1 = zz;
                #pragma unroll
                for (int k = 0; k < 8; ++k) {
                    ulonglong2 wva = wA[k];
                    ulonglong2 wvb = wB[k];
                    a0 = f2_fma(wva.x, hqA[2 * k], a0);
                    a1 = f2_fma(wva.y, hqA[2 * k + 1], a1);
                    b0 = f2_fma(wvb.x, hqA[2 * k], b0);
                    b1 = f2_fma(wvb.y, hqA[2 * k + 1], b1);
                    c0 = f2_fma(wva.x, hqB[2 * k], c0);
                    c1 = f2_fma(wva.y, hqB[2 * k + 1], c1);
                    d0 = f2_fma(wvb.x, hqB[2 * k], d0);
                    d1 = f2_fma(wvb.y, hqB[2 * k + 1], d1);
                }
                float p0, p1, p2, p3;
                const float biasA = sB2[net][oA], biasB = sB2[net][oA + 1];
                f2_unpack(a0, p0, p1); f2_unpack(a1, p2, p3);
                float xA0 = fmaxf(biasA + ((p0 + p1) + (p2 + p3)), 0.0f);
                f2_unpack(b0, p0, p1); f2_unpack(b1, p2, p3);
                float xA1 = fmaxf(biasB + ((p0 + p1) + (p2 + p3)), 0.0f);
                f2_unpack(c0, p0, p1); f2_unpack(c1, p2, p3);
                float xB0 = fmaxf(biasA + ((p0 + p1) + (p2 + p3)), 0.0f);
                f2_unpack(d0, p0, p1); f2_unpack(d1, p2, p3);
                float xB1 = fmaxf(biasB + ((p0 + p1) + (p2 + p3)), 0.0f);
                sXb[net][q * 4 + p][lane]      = f2_pack(xA0, xA1);
                sXb[net][q * 4 + p][lane + 16] = f2_pack(xB0, xB1);
            }
            __syncthreads();

            // L3: quarter 0 computes scalar outputs for both paths
            if (q == 0) {
                const ulonglong2* w = reinterpret_cast<const ulonglong2*>(&sW3[net][0]);
                unsigned long long a0 = zz, a1 = zz, c0 = zz, c1 = zz;
                #pragma unroll
                for (int k = 0; k < 8; ++k) {
                    ulonglong2 wv = w[k];
                    a0 = f2_fma(wv.x, sXb[net][2 * k][lane], a0);
                    a1 = f2_fma(wv.y, sXb[net][2 * k + 1][lane], a1);
                    c0 = f2_fma(wv.x, sXb[net][2 * k][lane + 16], c0);
                    c1 = f2_fma(wv.y, sXb[net][2 * k + 1][lane + 16], c1);
                }
                float r0, r1, r2, r3;
                f2_unpack(a0, r0, r1); f2_unpack(a1, r2, r3);
                float rawA = sB3[net] + ((r0 + r1) + (r2 + r3));
                f2_unpack(c0, r0, r1); f2_unpack(c1, r2, r3);
                float rawB = sB3[net] + ((r0 + r1) + (r2 + r3));
                sVal[net][lane]      = rawA / (1.0f + fabsf(rawA) * SQDT);
                sVal[net][lane + 16] = rawB / (1.0f + fabsf(rawB) * SQDT);
            }
            __syncthreads();

            const float v0A = sVal[0][lane], v0B = sVal[0][lane + 16];
            const float v1A = sVal[1][lane], v1B = sVal[1][lane + 16];
            const float v2A = sVal[2][lane], v2B = sVal[2][lane + 16];

            const float z1A = n1g[s * BB + bA], z1B = n1g[s * BB + bB];
            const float z2A = n2g[s * BB + bA], z2B = n2g[s * BB + bB];
            const float dWA = SQDT * z2A, dWB = SQDT * z2B;
            const float dBA = rho_s * dWA + rho_c * SQDT * z1A;
            const float dBB = rho_s * dWB + rho_c * SQDT * z1B;
            const float srA = SA * RFRF, srB = SB * RFRF;
            const float bSA = srA / (1.0f + fabsf(srA) * SQDT);
            const float bSB = srB / (1.0f + fabsf(srB) * SQDT);

            if (grp == 0) {
                g_Sin[s * BB + bA] = SA;
                g_Sin[s * BB + bB] = SB;
                const float ccA = DFF * SA * v0A * dWA;
                const float ccB = DFF * SB * v0B * dWB;
                g_c[s * BB + bA] = ccA;
                g_c[s * BB + bB] = ccB;
                csumA += ccA;
                csumB += ccB;
            }
            SA = SA + bSA * DTF + v0A * dBA;
            VA = fmaxf(VA + v1A * DTF + v2A * dWA, 0.0f);
            SB = SB + bSB * DTF + v0B * dBB;
            VB = fmaxf(VB + v1B * DTF + v2B * dWB, 0.0f);
        }
        if (grp == 0) {
            g_Ssnap[m * BB + bA] = SA;
            g_Ssnap[m * BB + bB] = SB;
            g_Cs[m * BB + bA] = csumA;
            g_Cs[m * BB + bB] = csumB;
            csumA = 0.0f;
            csumB = 0.0f;
        }
    }
}

// ---------------------------------------------------------------------------
// Kernel B (v8): hedge trunk — o-split across 2 thread-halves, 512 threads,
// 16 warps/SM (4/SMSP). thread = (ps, oh): paths (bA, bB) and 32 output
// neurons [oh*32, oh*32+32) per layer. All layers j-loop over a shared
// packed xbuf (reused L1->L2->L3 with barriers). Feature accumulation via
// global RMW into g_Fpart (L2-resident). smem = 181,760 B -> 1 block/SM.
// ---------------------------------------------------------------------------
__global__ void __launch_bounds__(512) hedge_kernel(
    const float* __restrict__ hW0, const float* __restrict__ hb0,
    const float* __restrict__ hW1, const float* __restrict__ hb1,
    const float* __restrict__ hW2, const float* __restrict__ hb2,
    const float* __restrict__ hW3, const float* __restrict__ hb3)
{
    extern __shared__ float sm[];
    float* w0   = sm;            // 128
    float* b0s  = w0 + 128;      // 64
    float* b1s  = b0s + 64;      // 64
    float* b2s  = b1s + 64;      // 64
    float* b3s  = b2s + 64;      // 64
    float* wT1  = b3s + 64;      // 4096  [j][o]
    float* wT2  = wT1 + 4096;    // 4096  [j][o]
    float* wT3  = wT2 + 4096;    // 4096  [j][o]
    unsigned long long* xbufU = reinterpret_cast<unsigned long long*>(wT3 + 4096); // [64][256]

    const int tid = threadIdx.x;
    const int ps  = tid & 255;          // path slot
    const int oh  = tid >> 8;           // 0/1 output half
    const int ob  = oh * 32;            // o base
    const int by  = blockIdx.y;         // 0..7 = m*2 + half
    const int m   = by >> 1;
    const int s0  = m * PER + (by & 1) * 12;
    const int bA  = blockIdx.x * 512 + ps;
    const int bB  = bA + 256;

    if (tid < 64) {
        b0s[tid] = hb0[m * 64 + tid];
        b1s[tid] = hb1[m * 64 + tid];
        b2s[tid] = hb2[m * 64 + tid];
        b3s[tid] = hb3[m * 64 + tid];
    } else if (tid < 192) {
        w0[tid - 64] = hW0[m * 128 + tid - 64];
    }
    for (int i = tid; i < 4096; i += 512) {
        int o = i >> 6, j = i & 63;
        wT1[j * 64 + o] = hW1[m * 4096 + i];
        wT2[j * 64 + o] = hW2[m * 4096 + i];
        wT3[j * 64 + o] = hW3[m * 4096 + i];
    }
    __syncthreads();

    const unsigned long long zz = f2_pack(0.0f, 0.0f);

    #pragma unroll 1
    for (int it = 0; it < 12; ++it) {
        const int s = s0 + it;
        const float t = (float)s * DTF;
        const float SA = g_Sin[s * BB + bA];
        const float SB = g_Sin[s * BB + bB];
        const float cA = g_c[s * BB + bA];
        const float cB = g_c[s * BB + bB];

        unsigned long long yA[16], yB[16];

        // ---- L1: j-loop, L0 inline; this half's 32 outputs ----
        {
            const ulonglong2* bv = reinterpret_cast<const ulonglong2*>(b1s + ob);
            #pragma unroll
            for (int k = 0; k < 8; ++k) {
                ulonglong2 v = bv[k];
                yA[2 * k] = v.x; yA[2 * k + 1] = v.y;
                yB[2 * k] = v.x; yB[2 * k + 1] = v.y;
            }
        }
        #pragma unroll 2
        for (int j = 0; j < 64; ++j) {
            const float w0a = w0[2 * j], w0b = w0[2 * j + 1], bj = b0s[j];
            const float xjA = fmaxf(bj + w0a * t + w0b * SA, 0.0f);
            const float xjB = fmaxf(bj + w0a * t + w0b * SB, 0.0f);
            const unsigned long long xpA = f2_pack(xjA, xjA);
            const unsigned long long xpB = f2_pack(xjB, xjB);
            const ulonglong2* w = reinterpret_cast<const ulonglong2*>(&wT1[j * 64 + ob]);
            #pragma unroll
            for (int k = 0; k < 8; ++k) {
                ulonglong2 wv = w[k];
                yA[2 * k]     = f2_fma(wv.x, xpA, yA[2 * k]);
                yA[2 * k + 1] = f2_fma(wv.y, xpA, yA[2 * k + 1]);
                yB[2 * k]     = f2_fma(wv.x, xpB, yB[2 * k]);
                yB[2 * k + 1] = f2_fma(wv.y, xpB, yB[2 * k + 1]);
            }
        }
        // relu -> xbuf (packed across paths): this half writes j = ob..ob+31
        #pragma unroll
        for (int p = 0; p < 16; ++p) {
            float a0, a1, c0, c1;
            f2_unpack(yA[p], a0, a1);
            f2_unpack(yB[p], c0, c1);
            xbufU[(ob + 2 * p) * 256 + ps]     = f2_pack(fmaxf(a0, 0.0f), fmaxf(c0, 0.0f));
            xbufU[(ob + 2 * p + 1) * 256 + ps] = f2_pack(fmaxf(a1, 0.0f), fmaxf(c1, 0.0f));
        }
        __syncthreads();

        // ---- L2: j-loop over full xbuf; this half's 32 outputs ----
        {
            const ulonglong2* bv = reinterpret_cast<const ulonglong2*>(b2s + ob);
            #pragma unroll
            for (int k = 0; k < 8; ++k) {
                ulonglong2 v = bv[k];
                yA[2 * k] = v.x; yA[2 * k + 1] = v.y;
                yB[2 * k] = v.x; yB[2 * k + 1] = v.y;
            }
        }
        #pragma unroll 2
        for (int j = 0; j < 64; ++j) {
            float xjA, xjB;
            f2_unpack(xbufU[j * 256 + ps], xjA, xjB);
            const unsigned long long xpA = f2_pack(xjA, xjA);
            const unsigned long long xpB = f2_pack(xjB, xjB);
            const ulonglong2* w = reinterpret_cast<const ulonglong2*>(&wT2[j * 64 + ob]);
            #pragma unroll
            for (int k = 0; k < 8; ++k) {
                ulonglong2 wv = w[k];
                yA[2 * k]     = f2_fma(wv.x, xpA, yA[2 * k]);
                yA[2 * k + 1] = f2_fma(wv.y, xpA, yA[2 * k + 1]);
                yB[2 * k]     = f2_fma(wv.x, xpB, yB[2 * k]);
                yB[2 * k + 1] = f2_fma(wv.y, xpB, yB[2 * k + 1]);
            }
        }
        __syncthreads();   // all L2 reads of xbuf complete before overwrite
        #pragma unroll
        for (int p = 0; p < 16; ++p) {
            float a0, a1, c0, c1;
            f2_unpack(yA[p], a0, a1);
            f2_unpack(yB[p], c0, c1);
            xbufU[(ob + 2 * p) * 256 + ps]     = f2_pack(fmaxf(a0, 0.0f), fmaxf(c0, 0.0f));
            xbufU[(ob + 2 * p + 1) * 256 + ps] = f2_pack(fmaxf(a1, 0.0f), fmaxf(c1, 0.0f));
        }
        __syncthreads();

        // ---- L3: j-loop over full xbuf; this half's 32 w3-rows ----
        #pragma unroll
        for (int k = 0; k < 16; ++k) { yA[k] = zz; yB[k] = zz; }
        #pragma unroll 2
        for (int j = 0; j < 64; ++j) {
            float xjA, xjB;
            f2_unpack(xbufU[j * 256 + ps], xjA, xjB);
            const unsigned long long xpA = f2_pack(xjA, xjA);
            const unsigned long long xpB = f2_pack(xjB, xjB);
            const ulonglong2* w = reinterpret_cast<const ulonglong2*>(&wT3[j * 64 + ob]);
            #pragma unroll
            for (int k = 0; k < 8; ++k) {
                ulonglong2 wv = w[k];
                yA[2 * k]     = f2_fma(wv.x, xpA, yA[2 * k]);
                yA[2 * k + 1] = f2_fma(wv.y, xpA, yA[2 * k + 1]);
                yB[2 * k]     = f2_fma(wv.x, xpB, yB[2 * k]);
                yB[2 * k + 1] = f2_fma(wv.y, xpB, yB[2 * k + 1]);
            }
        }
        // finish: relu(b3 + acc), accumulate c*h into g_Fpart
        #pragma unroll
        for (int p = 0; p < 16; ++p) {
            const int o = ob + 2 * p;
            float a0, a1, c0, c1;
            f2_unpack(yA[p], a0, a1);
            f2_unpack(yB[p], c0, c1);
            const float b3a = b3s[o], b3b = b3s[o + 1];
            float hA0 = fmaxf(b3a + a0, 0.0f);
            float hA1 = fmaxf(b3b + a1, 0.0f);
            float hB0 = fmaxf(b3a + c0, 0.0f);
            float hB1 = fmaxf(b3b + c1, 0.0f);
            const size_t idx = (size_t)(by * 64 + o) * BB + bA;
            g_Fpart[idx]            += cA * hA0;
            g_Fpart[idx + BB]       += cA * hA1;
            g_Fpart[idx + 256]      += cB * hB0;
            g_Fpart[idx + BB + 256] += cB * hB1;
        }
        __syncthreads();   // protect xbuf before next step's L1 writes
    }
}

// ---------------------------------------------------------------------------
// Kernel C (v6): masked-q GEMM producing H directly; 32-row o-tiles,
// 2 blocks/SM (__launch_bounds__(256,2)), grid (32, 26).
// ---------------------------------------------------------------------------
__global__ void __launch_bounds__(256, 2) gemmH_kernel(
    const float* __restrict__ hW4, const float* __restrict__ hb4)
{
    __shared__ __align__(16) float As[32 * 64];
    __shared__ float sB4[4 * 32];

    const int tid = threadIdx.x;
    const int m0  = blockIdx.y * 32;
    const int n   = blockIdx.x * 256 + tid;

    if (tid < 128) {
        int qq = tid >> 5, oo = tid & 31;
        int o = m0 + oo;
        sB4[tid] = (o < NOUTS) ? hb4[qq * NOUTS + o] : 0.0f;
    }

    float acc[32];
    #pragma unroll
    for (int oo = 0; oo < 32; ++oo) acc[oo] = 0.0f;

    const unsigned long long zz = f2_pack(0.0f, 0.0f);

    #pragma unroll 1
    for (int q = 0; q < 4; ++q) {
        __syncthreads();
        for (int i = tid; i < 32 * 64; i += 256) {
            int oo = i >> 6, o = m0 + oo;
            As[i] = (o < NOUTS) ? hW4[(size_t)(q * NOUTS + o) * 64 + (i & 63)] : 0.0f;
        }
        __syncthreads();

        unsigned long long xU[32];
        #pragma unroll
        for (int p = 0; p < 32; ++p) {
            float a = g_Fpart[(size_t)((2 * q) * 64 + 2 * p) * BB + n]
                    + g_Fpart[(size_t)((2 * q + 1) * 64 + 2 * p) * BB + n];
            float b = g_Fpart[(size_t)((2 * q) * 64 + 2 * p + 1) * BB + n]
                    + g_Fpart[(size_t)((2 * q + 1) * 64 + 2 * p + 1) * BB + n];
            xU[p] = f2_pack(a, b);
        }

        #pragma unroll
        for (int mm = 0; mm < 4; ++mm) {
            if (q <= mm) {
                #pragma unroll
                for (int jj = 0; jj < 8; ++jj) {
                    const int oo = jj * 4 + mm;
                    const ulonglong2* w = reinterpret_cast<const ulonglong2*>(&As[oo * 64]);
                    unsigned long long a0 = zz, a1 = zz;
                    #pragma unroll
                    for (int k = 0; k < 16; ++k) {
                        ulonglong2 wv = w[k];
                        a0 = f2_fma(wv.x, xU[2 * k], a0);
                        a1 = f2_fma(wv.y, xU[2 * k + 1], a1);
                    }
                    float r0, r1, r2, r3;
                    f2_unpack(a0, r0, r1);
                    f2_unpack(a1, r2, r3);
                    acc[oo] += ((r0 + r1) + (r2 + r3));
                }
            }
        }
    }

    const float Cs0 = g_Cs[n],          Cs1 = g_Cs[BB + n];
    const float Cs2 = g_Cs[2 * BB + n], Cs3 = g_Cs[3 * BB + n];

    #pragma unroll
    for (int oo = 0; oo < 32; ++oo) {
        const int o = m0 + oo;
        if (o < NOUTS) {
            const int m = oo & 3;
            float H = acc[oo] + sB4[oo] * Cs0;
            if (m >= 1) H += sB4[32 + oo] * Cs1;
            if (m >= 2) H += sB4[64 + oo] * Cs2;
            if (m >= 3) H += sB4[96 + oo] * Cs3;
            g_H[(size_t)o * BB + n] = H;
        }
    }
}

// ---------------------------------------------------------------------------
// Kernel D (v3): payoff + mean/variance per (strike, maturity); fp64 acc.
// ---------------------------------------------------------------------------
__global__ void __launch_bounds__(512) reduce_kernel(
    const float* __restrict__ strikes, float* __restrict__ out)
{
    const int o = blockIdx.x;          // 0..803, o = k*4 + m
    const int k = o >> 2;
    const int m = o & 3;
    const int tid = threadIdx.x;
    const float disc = (float)exp(-0.025 * (double)(m + 1));
    const float K = strikes[k];

    double sum = 0.0, ss = 0.0;
    for (int b = tid; b < BB; b += 512) {
        float pay = disc * fmaxf(g_Ssnap[m * BB + b] - K, 0.0f) - g_H[(size_t)o * BB + b];
        sum += (double)pay;
        ss += (double)pay * (double)pay;
    }

    __shared__ double r1[512], r2[512];
    r1[tid] = sum; r2[tid] = ss;
    __syncthreads();
    for (int st = 256; st > 0; st >>= 1) {
        if (tid < st) { r1[tid] += r1[tid + st]; r2[tid] += r2[tid + st]; }
        __syncthreads();
    }
    if (tid == 0) {
        double total = r1[0];
        out[o] = (float)(total / 8192.0);
        out[NOUTS + o] = (float)((r2[0] - total * total / 8192.0) / 8191.0);
    }
}

// ---------------------------------------------------------------------------
extern "C" void kernel_launch(void* const* d_in, const int* in_sizes, int n_in,
                              void* d_out, int out_size)
{
    const float* nW0 = (const float*)d_in[0];
    const float* nb0 = (const float*)d_in[1];
    const float* nW1 = (const float*)d_in[2];
    const float* nb1 = (const float*)d_in[3];
    const float* nW2 = (const float*)d_in[4];
    const float* nb2 = (const float*)d_in[5];
    const float* nW3 = (const float*)d_in[6];
    const float* nb3 = (const float*)d_in[7];
    const float* hW0 = (const float*)d_in[8];
    const float* hb0 = (const float*)d_in[9];
    const float* hW1 = (const float*)d_in[10];
    const float* hb1 = (const float*)d_in[11];
    const float* hW2 = (const float*)d_in[12];
    const float* hb2 = (const float*)d_in[13];
    const float* hW3 = (const float*)d_in[14];
    const float* hb3 = (const float*)d_in[15];
    const float* hW4 = (const float*)d_in[16];
    const float* hb4 = (const float*)d_in[17];
    const float* rho = (const float*)d_in[18];
    const float* V0  = (const float*)d_in[19];
    const float* strikes = (const float*)d_in[20];
    const float* noise1  = (const float*)d_in[21];
    const float* noise2  = (const float*)d_in[22];

    const int hedge_smem = 45440 * (int)sizeof(float);  // 181,760 B
    cudaFuncSetAttribute(hedge_kernel, cudaFuncAttributeMaxDynamicSharedMemorySize,
                         hedge_smem);

    zero_fpart<<<(8 * 64 * BB) / 1024, 1024>>>();
    sim_kernel<<<256, 192>>>(nW0, nb0, nW1, nb1, nW2, nb2, nW3, nb3,
                             rho, V0, noise1, noise2);
    hedge_kernel<<<dim3(16, 8), 512, hedge_smem>>>(hW0, hb0, hW1, hb1,
                                                   hW2, hb2, hW3, hb3);
    gemmH_kernel<<<dim3(32, 26), 256>>>(hW4, hb4);
    reduce_kernel<<<NOUTS, 512>>>(strikes, (float*)d_out);
}